// round 9
// baseline (speedup 1.0000x reference)
#include <cuda_runtime.h>
#include <cuda_bf16.h>
#include <cuda_fp16.h>
#include <math.h>

#define Bb 2
#define Ss 128
#define Hh 768
#define Cc 5
#define NEGV (-1024.0f)
#define Mm (Bb*Ss)          // 256
#define NTOT (Hh + Cc*Hh)   // 4608
#define NROWS (Bb*Ss*Cc)    // 1280
#define OUTN (Bb*Ss*Cc*Ss)  // 163840

#define KG  (Hh/16)         // 48
#define MI  (Mm/16)         // 16
#define NI8 (NTOT/8)        // 576

#define SEG 8
#define HSEG (Hh/SEG)       // 96
#define JP2 (HSEG/2)        // 48 half2 columns per segment
#define HH2 (Hh/2)          // 384

__device__ __half g_hp_h[Mm*Hh];        // f16 h_p (written by gemm epilogue)
__device__ __half g_ha_h[Mm*Cc*Hh];     // f16 h_a
__device__ float g_part[SEG*OUTN];
__device__ float g_rnum[NROWS];
__device__ float g_rden[NROWS];
__device__ float g_maskadd[Bb*Ss*Ss];
__device__ int   g_ngMode;
__device__ unsigned g_ctr;
__device__ unsigned g_Afh[KG*MI*32*4];
__device__ unsigned g_Afl[KG*MI*32*4];
__device__ unsigned g_Bfh[KG*NI8*32*2];
__device__ unsigned g_Bfl[KG*NI8*32*2];

__device__ __forceinline__ unsigned pack2(__nv_bfloat16 lo, __nv_bfloat16 hi){
    __nv_bfloat162 v; v.x = lo; v.y = hi;
    return *reinterpret_cast<unsigned*>(&v);
}
__device__ __forceinline__ void split_bf(float x, __nv_bfloat16& h, __nv_bfloat16& l){
    h = __float2bfloat16(x);
    l = __float2bfloat16(x - __bfloat162float(h));
}

// ---------------------------------------------------------------------------
__global__ __launch_bounds__(256) void k_detect(const unsigned char* __restrict__ ng){
    __shared__ int s_b1, s_f3;
    if (threadIdx.x == 0){ s_b1 = 0; s_f3 = 0; }
    __syncthreads();
    int b1 = 0, f3 = 0;
    for (int i = threadIdx.x; i < 16384; i += 256){
        unsigned char v = ng[i];
        int o = i & 3;
        if (o == 1 && v) b1 = 1;
        if (o == 3 && v == 0x3F) f3 = 1;
    }
    if (b1) s_b1 = 1;
    if (f3) s_f3 = 1;
    __syncthreads();
    if (threadIdx.x == 0) g_ngMode = s_b1 ? 0 : (s_f3 ? 2 : 1);
}

__device__ __forceinline__ bool ng_bit(const void* ng, int idx, int mode){
    if (mode == 1) return ((const int*)ng)[idx] != 0;
    if (mode == 2) return ((const float*)ng)[idx] != 0.0f;
    return ((const unsigned char*)ng)[idx] != 0;
}

// ---------------------------------------------------------------------------
#define AW (KG*MI*32*4)
#define BW (KG*NI8*32*2)
#define MW (Bb*Ss*Ss)
#define PREPTOT (AW+BW+MW)

__global__ __launch_bounds__(256) void k_prep(const float* __restrict__ X,
        const float* __restrict__ Wp, const float* __restrict__ Wa,
        const int* __restrict__ att, const void* __restrict__ ng){
    int idx = blockIdx.x*256 + threadIdx.x;
    if (idx < AW){
        int w = idx;
        int reg = w & 3, lane = (w>>2)&31;
        int tile = w>>7;
        int mi = tile % MI, g = tile / MI;
        int m = mi*16 + (lane>>2) + (reg&1)*8;
        int k = g*16 + (lane&3)*2 + (reg>>1)*8;
        float2 v = *(const float2*)&X[m*Hh + k];
        __nv_bfloat16 hx,lx,hy,ly;
        split_bf(v.x, hx, lx); split_bf(v.y, hy, ly);
        g_Afh[w] = pack2(hx, hy);
        g_Afl[w] = pack2(lx, ly);
    } else if (idx < AW + BW){
        int w = idx - AW;
        int reg = w & 1, lane = (w>>1)&31;
        int tile = w>>6;
        int ni = tile % NI8, g = tile / NI8;
        int n = ni*8 + (lane>>2);
        int k = g*16 + (lane&3)*2 + reg*8;
        float2 v = (n < Hh) ? *(const float2*)&Wp[n*Hh + k]
                            : *(const float2*)&Wa[(n-Hh)*Hh + k];
        __nv_bfloat16 hx,lx,hy,ly;
        split_bf(v.x, hx, lx); split_bf(v.y, hy, ly);
        g_Bfh[w] = pack2(hx, hy);
        g_Bfl[w] = pack2(lx, ly);
    } else if (idx < PREPTOT){
        int w = idx - AW - BW;
        int a = w & 127;
        int bp_ = w >> 7;
        int b = bp_ >> 7;
        int mode = g_ngMode;
        bool attv = att[b*Ss + a] > 0;
        bool m = false;
        #pragma unroll
        for (int c = 0; c < Cc; c++)
            m = m || ng_bit(ng, (bp_*Cc + c)*Ss + a, mode);
        g_maskadd[w] = (m && attv) ? 0.0f : NEGV;
    }
}

// ---------------------------------------------------------------------------
// GEMM: mma m16n8k16 bf16, acc += Ah*Bh + Ah*Bl + Al*Bh, double-buffered.
// Epilogue converts to f16 and stores g_hp_h / g_ha_h (half2 stores).
// ---------------------------------------------------------------------------
__device__ __forceinline__ void mma_bf16(float& d0, float& d1, float& d2, float& d3,
        unsigned a0, unsigned a1, unsigned a2, unsigned a3,
        unsigned b0, unsigned b1){
    asm volatile("mma.sync.aligned.m16n8k16.row.col.f32.bf16.bf16.f32 "
        "{%0,%1,%2,%3}, {%4,%5,%6,%7}, {%8,%9}, {%0,%1,%2,%3};"
        : "+f"(d0), "+f"(d1), "+f"(d2), "+f"(d3)
        : "r"(a0), "r"(a1), "r"(a2), "r"(a3), "r"(b0), "r"(b1));
}

__global__ __launch_bounds__(256) void k_gemm(const float* __restrict__ bp,
                                              const float* __restrict__ ba){
    int tid = threadIdx.x;
    int wid = tid >> 5, lane = tid & 31;
    int wr = wid >> 2, wc = wid & 3;
    int mi0 = blockIdx.y*8 + wr*4;
    int ni0 = blockIdx.x*8 + wc*2;

    float acc[4][2][4];
    #pragma unroll
    for (int i=0;i<4;i++) for (int j=0;j<2;j++) for (int q=0;q<4;q++) acc[i][j][q]=0.f;

    const uint4* pAh = reinterpret_cast<const uint4*>(g_Afh);
    const uint4* pAl = reinterpret_cast<const uint4*>(g_Afl);
    const uint2* pBh = reinterpret_cast<const uint2*>(g_Bfh);
    const uint2* pBl = reinterpret_cast<const uint2*>(g_Bfl);

    uint4 Ah[4], Al[4]; uint2 Bh[2], Bl[2];
    #pragma unroll
    for (int mf=0; mf<4; mf++){
        int t = (0*MI + mi0+mf)*32 + lane;
        Ah[mf] = pAh[t]; Al[mf] = pAl[t];
    }
    #pragma unroll
    for (int nf=0; nf<2; nf++){
        int t = (0*NI8 + ni0+nf)*32 + lane;
        Bh[nf] = pBh[t]; Bl[nf] = pBl[t];
    }

    for (int g = 0; g < KG; g++){
        uint4 An[4], Aln[4]; uint2 Bn[2], Bln[2];
        if (g+1 < KG){
            #pragma unroll
            for (int mf=0; mf<4; mf++){
                int t = ((g+1)*MI + mi0+mf)*32 + lane;
                An[mf] = pAh[t]; Aln[mf] = pAl[t];
            }
            #pragma unroll
            for (int nf=0; nf<2; nf++){
                int t = ((g+1)*NI8 + ni0+nf)*32 + lane;
                Bn[nf] = pBh[t]; Bln[nf] = pBl[t];
            }
        }
        #pragma unroll
        for (int mf=0; mf<4; mf++)
            #pragma unroll
            for (int nf=0; nf<2; nf++){
                mma_bf16(acc[mf][nf][0], acc[mf][nf][1], acc[mf][nf][2], acc[mf][nf][3],
                         Ah[mf].x, Ah[mf].y, Ah[mf].z, Ah[mf].w, Bh[nf].x, Bh[nf].y);
                mma_bf16(acc[mf][nf][0], acc[mf][nf][1], acc[mf][nf][2], acc[mf][nf][3],
                         Ah[mf].x, Ah[mf].y, Ah[mf].z, Ah[mf].w, Bl[nf].x, Bl[nf].y);
                mma_bf16(acc[mf][nf][0], acc[mf][nf][1], acc[mf][nf][2], acc[mf][nf][3],
                         Al[mf].x, Al[mf].y, Al[mf].z, Al[mf].w, Bh[nf].x, Bh[nf].y);
            }
        if (g+1 < KG){
            #pragma unroll
            for (int mf=0; mf<4; mf++){ Ah[mf]=An[mf]; Al[mf]=Aln[mf]; }
            #pragma unroll
            for (int nf=0; nf<2; nf++){ Bh[nf]=Bn[nf]; Bl[nf]=Bln[nf]; }
        }
    }

    int r = lane >> 2, c2 = (lane & 3)*2;
    #pragma unroll
    for (int nf=0; nf<2; nf++){
        int n = (ni0+nf)*8 + c2;
        float2 bias = (n < Hh) ? *(const float2*)&bp[n] : *(const float2*)&ba[n-Hh];
        #pragma unroll
        for (int mf=0; mf<4; mf++){
            int m1 = (mi0+mf)*16 + r;
            int m2 = m1 + 8;
            __half2 v1 = __floats2half2_rn(acc[mf][nf][0] + bias.x, acc[mf][nf][1] + bias.y);
            __half2 v2 = __floats2half2_rn(acc[mf][nf][2] + bias.x, acc[mf][nf][3] + bias.y);
            if (n < Hh){
                *(__half2*)&g_hp_h[m1*Hh + n] = v1;
                *(__half2*)&g_hp_h[m2*Hh + n] = v2;
            } else {
                *(__half2*)&g_ha_h[m1*(Cc*Hh) + (n-Hh)] = v1;
                *(__half2*)&g_ha_h[m2*(Cc*Hh) + (n-Hh)] = v2;
            }
        }
    }
}

// ---------------------------------------------------------------------------
// biaffine partial: all-f16x2. 8-way h-split, tile 32p x 16a, 256 threads
// (thread = rows p, p+16 at column a). Loads are raw half2 copies.
// grid = 512: seg = bx&7; rest = bx>>3 -> b(1) x ptile(4) x atile(8)
// ---------------------------------------------------------------------------
__global__ __launch_bounds__(256,4) void k_biaffine(const float* __restrict__ Wout){
    __shared__ __half2 s_hp[32][JP2+1];
    __shared__ __half2 s_ha[Cc][JP2][17];
    __shared__ __half2 s_w[Cc][JP2];
    int bx = blockIdx.x;
    int seg  = bx & 7;
    int rest = bx >> 3;               // 0..63
    int b   = rest >> 5;
    int rem = rest & 31;
    int p0 = (rem >> 3) * 32;
    int a0 = (rem & 7)  * 16;
    int tid = threadIdx.x;
    int p = tid >> 4, a = tid & 15;   // p 0..15, a 0..15
    int jbase = seg * JP2;            // half2 offset into row

    const __half2* HP = reinterpret_cast<const __half2*>(g_hp_h);
    const __half2* HA = reinterpret_cast<const __half2*>(g_ha_h);

    #pragma unroll
    for (int i = 0; i < 6; i++){                  // 32*48 = 1536 half2
        int idx = tid + i*256;
        int r = idx / JP2, jp = idx % JP2;
        s_hp[r][jp] = HP[(b*Ss + p0 + r)*HH2 + jbase + jp];
    }
    #pragma unroll
    for (int i = 0; i < 15; i++){                 // 16*5*48 = 3840 half2
        int idx = tid + i*256;
        int al = idx / (Cc*JP2);
        int rr = idx % (Cc*JP2);
        int c = rr / JP2, jp = rr % JP2;
        s_ha[c][jp][al] = HA[((b*Ss + a0 + al)*Cc + c)*HH2 + jbase + jp];
    }
    for (int idx = tid; idx < Cc*JP2; idx += 256){
        int c = idx / JP2, jp = idx % JP2;
        float2 v = *(const float2*)&Wout[c*Hh + seg*HSEG + 2*jp];
        s_w[c][jp] = __floats2half2_rn(v.x, v.y);
    }
    __syncthreads();

    float fA[Cc] = {}, fB[Cc] = {};
    #pragma unroll 1
    for (int blk = 0; blk < 4; blk++){            // 4 blocks of 12 jp
        __half2 accA[Cc], accB[Cc];
        #pragma unroll
        for (int c=0;c<Cc;c++){
            accA[c] = __floats2half2_rn(0.f, 0.f);
            accB[c] = __floats2half2_rn(0.f, 0.f);
        }
        #pragma unroll
        for (int j=0;j<12;j++){
            int jp = blk*12 + j;
            __half2 hpA = s_hp[p][jp];
            __half2 hpB = s_hp[p+16][jp];
            #pragma unroll
            for (int c=0;c<Cc;c++){
                __half2 ha = s_ha[c][jp][a];
                __half2 w  = s_w[c][jp];
                __half2 xA = __hadd2(hpA, ha);
                __half2 xB = __hadd2(hpB, ha);
                unsigned tA, tB;
                asm("tanh.approx.f16x2 %0, %1;" : "=r"(tA) : "r"(*(unsigned*)&xA));
                asm("tanh.approx.f16x2 %0, %1;" : "=r"(tB) : "r"(*(unsigned*)&xB));
                accA[c] = __hfma2(*(__half2*)&tA, w, accA[c]);
                accB[c] = __hfma2(*(__half2*)&tB, w, accB[c]);
            }
        }
        #pragma unroll
        for (int c=0;c<Cc;c++){
            float2 vA = __half22float2(accA[c]);
            float2 vB = __half22float2(accB[c]);
            fA[c] += vA.x + vA.y;
            fB[c] += vB.x + vB.y;
        }
    }
    int pgA = p0 + p, pgB = p0 + p + 16, ag = a0 + a;
    #pragma unroll
    for (int c=0;c<Cc;c++){
        g_part[seg*OUTN + ((b*Ss+pgA)*Cc + c)*Ss + ag] = fA[c];
        g_part[seg*OUTN + ((b*Ss+pgB)*Cc + c)*Ss + ag] = fB[c];
    }
}

// ---------------------------------------------------------------------------
// combine: sum 8 partials + maskadd, write dst, fused row log-softmax CE,
// and last-block finalize (fence+counter).
// ---------------------------------------------------------------------------
#define NBLK (OUTN/256)   // 640

__global__ __launch_bounds__(256) void k_combine(const float* __restrict__ targ,
        float* __restrict__ dst, float* __restrict__ out,
        int writeOut, int writeLoss){
    const unsigned FULL = 0xffffffffu;
    int tid = threadIdx.x;
    int i = blockIdx.x*256 + tid;
    float v = 0.f;
    #pragma unroll
    for (int k=0;k<SEG;k++) v += g_part[k*OUTN + i];
    int a = i & 127;
    int row = i >> 7;
    int bp = row / Cc;
    v += g_maskadd[bp*Ss + a];
    if (writeOut) dst[i] = v;

    int w = tid >> 5, lane = tid & 31, rg = tid >> 7;
    __shared__ float sA[8], sB[8];

    float m = v;
    #pragma unroll
    for (int o=16;o>0;o>>=1) m = fmaxf(m, __shfl_xor_sync(FULL,m,o));
    if (lane==0) sA[w] = m;
    __syncthreads();
    m = fmaxf(fmaxf(sA[rg*4+0],sA[rg*4+1]), fmaxf(sA[rg*4+2],sA[rg*4+3]));

    float e = __expf(v - m);
    float s = e;
    #pragma unroll
    for (int o=16;o>0;o>>=1) s += __shfl_xor_sync(FULL,s,o);
    if (lane==0) sB[w] = s;
    __syncthreads();
    s = sB[rg*4+0]+sB[rg*4+1]+sB[rg*4+2]+sB[rg*4+3];
    float logZ = __logf(s) + m;

    float tg = targ[i];
    float num = tg * (logZ - v);
    float den = tg;
    #pragma unroll
    for (int o=16;o>0;o>>=1){
        num += __shfl_xor_sync(FULL,num,o);
        den += __shfl_xor_sync(FULL,den,o);
    }
    __syncthreads();
    if (lane==0){ sA[w] = num; sB[w] = den; }
    __syncthreads();
    if ((tid & 127) == 0){
        int r = blockIdx.x*2 + rg;
        g_rnum[r] = sA[rg*4+0]+sA[rg*4+1]+sA[rg*4+2]+sA[rg*4+3];
        g_rden[r] = sB[rg*4+0]+sB[rg*4+1]+sB[rg*4+2]+sB[rg*4+3];
    }

    __threadfence();
    __shared__ unsigned s_rank;
    if (tid == 0) s_rank = atomicAdd(&g_ctr, 1u);
    __syncthreads();
    if (s_rank == NBLK-1){
        float n=0.f, d=0.f;
        for (int r = tid; r < NROWS; r += 256){ n += g_rnum[r]; d += g_rden[r]; }
        __shared__ float sn[256], sd[256];
        sn[tid]=n; sd[tid]=d; __syncthreads();
        for (int o=128;o>0;o>>=1){
            if (tid<o){ sn[tid]+=sn[tid+o]; sd[tid]+=sd[tid+o]; }
            __syncthreads();
        }
        if (tid==0){
            if (writeLoss) out[0] = sn[0]/sd[0];
            g_ctr = 0;
        }
    }
}

// ---------------------------------------------------------------------------
extern "C" void kernel_launch(void* const* d_in, const int* in_sizes, int n_in,
                              void* d_out, int out_size){
    const float*         seq  = (const float*)d_in[0];
    const int*           att  = (const int*)d_in[1];
    const unsigned char* ng   = (const unsigned char*)d_in[2];
    const float*         targ = (const float*)d_in[3];
    const float*         Wp   = (const float*)d_in[4];
    const float*         bp   = (const float*)d_in[5];
    const float*         Wa   = (const float*)d_in[6];
    const float*         ba   = (const float*)d_in[7];
    const float*         Wout = (const float*)d_in[8];
    float* out = (float*)d_out;

    k_detect<<<1, 256>>>(ng);
    k_prep<<<(PREPTOT+255)/256, 256>>>(seq, Wp, Wa, att, (const void*)ng);
    k_gemm<<<dim3(NTOT/64, Mm/128), 256>>>(bp, ba);
    k_biaffine<<<512, 256>>>(Wout);

    int wantLoss = (out_size != OUTN) ? 1 : 0;
    int wantOut  = (out_size >= OUTN) ? 1 : 0;
    float* dst = out + ((out_size > OUTN) ? 1 : 0);
    k_combine<<<NBLK, 256>>>(targ, dst, out, wantOut, wantLoss);
}

// round 10
// speedup vs baseline: 1.0907x; 1.0907x over previous
#include <cuda_runtime.h>
#include <cuda_bf16.h>
#include <cuda_fp16.h>
#include <math.h>

#define Bb 2
#define Ss 128
#define Hh 768
#define Cc 5
#define NEGV (-1024.0f)
#define Mm (Bb*Ss)          // 256
#define NTOT (Hh + Cc*Hh)   // 4608
#define NROWS (Bb*Ss*Cc)    // 1280
#define OUTN (Bb*Ss*Cc*Ss)  // 163840

#define KG  (Hh/16)         // 48
#define MI  (Mm/16)         // 16
#define NI8 (NTOT/8)        // 576

#define SEG 8
#define HSEG (Hh/SEG)       // 96
#define JP2 (HSEG/2)        // 48 half2 per segment
#define HH2 (Hh/2)          // 384

__device__ __half g_hp_h[Mm*Hh];
__device__ __half g_ha_h[Mm*Cc*Hh];
__device__ float g_part[SEG*OUTN];
__device__ float g_rnum[NROWS];
__device__ float g_rden[NROWS];
__device__ int   g_ngMode;
__device__ unsigned g_ctr;
__device__ unsigned g_Afh[KG*MI*32*4];
__device__ unsigned g_Afl[KG*MI*32*4];
__device__ unsigned g_Bfh[KG*NI8*32*2];
__device__ unsigned g_Bfl[KG*NI8*32*2];

__device__ __forceinline__ unsigned pack2(__nv_bfloat16 lo, __nv_bfloat16 hi){
    __nv_bfloat162 v; v.x = lo; v.y = hi;
    return *reinterpret_cast<unsigned*>(&v);
}
__device__ __forceinline__ void split_bf(float x, __nv_bfloat16& h, __nv_bfloat16& l){
    h = __float2bfloat16(x);
    l = __float2bfloat16(x - __bfloat162float(h));
}
__device__ __forceinline__ bool ng_bit(const void* ng, int idx, int mode){
    if (mode == 1) return ((const int*)ng)[idx] != 0;
    if (mode == 2) return ((const float*)ng)[idx] != 0.0f;
    return ((const unsigned char*)ng)[idx] != 0;
}

// ---------------------------------------------------------------------------
// prep: bf16 hi/lo fragments; LAST BLOCK does ng dtype detection.
// AW+BW = 1867776 = 7296*256 exactly; grid = 7297.
// ---------------------------------------------------------------------------
#define AW (KG*MI*32*4)      // 98304
#define BW (KG*NI8*32*2)     // 1769472
#define FRAGTOT (AW+BW)
#define PREP_BLOCKS (FRAGTOT/256 + 1)

__global__ __launch_bounds__(256) void k_prep(const float* __restrict__ X,
        const float* __restrict__ Wp, const float* __restrict__ Wa,
        const unsigned char* __restrict__ ng){
    if (blockIdx.x == PREP_BLOCKS-1){
        // detect ng storage dtype from byte pattern
        __shared__ int s_b1, s_f3;
        if (threadIdx.x == 0){ s_b1 = 0; s_f3 = 0; }
        __syncthreads();
        int b1 = 0, f3 = 0;
        for (int i = threadIdx.x; i < 16384; i += 256){
            unsigned char v = ng[i];
            int o = i & 3;
            if (o == 1 && v) b1 = 1;
            if (o == 3 && v == 0x3F) f3 = 1;
        }
        if (b1) s_b1 = 1;
        if (f3) s_f3 = 1;
        __syncthreads();
        if (threadIdx.x == 0) g_ngMode = s_b1 ? 0 : (s_f3 ? 2 : 1);
        return;
    }
    int idx = blockIdx.x*256 + threadIdx.x;
    if (idx < AW){
        int w = idx;
        int reg = w & 3, lane = (w>>2)&31;
        int tile = w>>7;
        int mi = tile % MI, g = tile / MI;
        int m = mi*16 + (lane>>2) + (reg&1)*8;
        int k = g*16 + (lane&3)*2 + (reg>>1)*8;
        float2 v = *(const float2*)&X[m*Hh + k];
        __nv_bfloat16 hx,lx,hy,ly;
        split_bf(v.x, hx, lx); split_bf(v.y, hy, ly);
        g_Afh[w] = pack2(hx, hy);
        g_Afl[w] = pack2(lx, ly);
    } else {
        int w = idx - AW;
        int reg = w & 1, lane = (w>>1)&31;
        int tile = w>>6;
        int ni = tile % NI8, g = tile / NI8;
        int n = ni*8 + (lane>>2);
        int k = g*16 + (lane&3)*2 + reg*8;
        float2 v = (n < Hh) ? *(const float2*)&Wp[n*Hh + k]
                            : *(const float2*)&Wa[(n-Hh)*Hh + k];
        __nv_bfloat16 hx,lx,hy,ly;
        split_bf(v.x, hx, lx); split_bf(v.y, hy, ly);
        g_Bfh[w] = pack2(hx, hy);
        g_Bfl[w] = pack2(lx, ly);
    }
}

// ---------------------------------------------------------------------------
// GEMM: mma m16n8k16 bf16, acc += Ah*Bh + Ah*Bl + Al*Bh, double-buffered.
// Epilogue stores f16 g_hp_h / g_ha_h.
// ---------------------------------------------------------------------------
__device__ __forceinline__ void mma_bf16(float& d0, float& d1, float& d2, float& d3,
        unsigned a0, unsigned a1, unsigned a2, unsigned a3,
        unsigned b0, unsigned b1){
    asm volatile("mma.sync.aligned.m16n8k16.row.col.f32.bf16.bf16.f32 "
        "{%0,%1,%2,%3}, {%4,%5,%6,%7}, {%8,%9}, {%0,%1,%2,%3};"
        : "+f"(d0), "+f"(d1), "+f"(d2), "+f"(d3)
        : "r"(a0), "r"(a1), "r"(a2), "r"(a3), "r"(b0), "r"(b1));
}

__global__ __launch_bounds__(256) void k_gemm(const float* __restrict__ bp,
                                              const float* __restrict__ ba){
    int tid = threadIdx.x;
    int wid = tid >> 5, lane = tid & 31;
    int wr = wid >> 2, wc = wid & 3;
    int mi0 = blockIdx.y*8 + wr*4;
    int ni0 = blockIdx.x*8 + wc*2;

    float acc[4][2][4];
    #pragma unroll
    for (int i=0;i<4;i++) for (int j=0;j<2;j++) for (int q=0;q<4;q++) acc[i][j][q]=0.f;

    const uint4* pAh = reinterpret_cast<const uint4*>(g_Afh);
    const uint4* pAl = reinterpret_cast<const uint4*>(g_Afl);
    const uint2* pBh = reinterpret_cast<const uint2*>(g_Bfh);
    const uint2* pBl = reinterpret_cast<const uint2*>(g_Bfl);

    uint4 Ah[4], Al[4]; uint2 Bh[2], Bl[2];
    #pragma unroll
    for (int mf=0; mf<4; mf++){
        int t = (0*MI + mi0+mf)*32 + lane;
        Ah[mf] = pAh[t]; Al[mf] = pAl[t];
    }
    #pragma unroll
    for (int nf=0; nf<2; nf++){
        int t = (0*NI8 + ni0+nf)*32 + lane;
        Bh[nf] = pBh[t]; Bl[nf] = pBl[t];
    }

    for (int g = 0; g < KG; g++){
        uint4 An[4], Aln[4]; uint2 Bn[2], Bln[2];
        if (g+1 < KG){
            #pragma unroll
            for (int mf=0; mf<4; mf++){
                int t = ((g+1)*MI + mi0+mf)*32 + lane;
                An[mf] = pAh[t]; Aln[mf] = pAl[t];
            }
            #pragma unroll
            for (int nf=0; nf<2; nf++){
                int t = ((g+1)*NI8 + ni0+nf)*32 + lane;
                Bn[nf] = pBh[t]; Bln[nf] = pBl[t];
            }
        }
        #pragma unroll
        for (int mf=0; mf<4; mf++)
            #pragma unroll
            for (int nf=0; nf<2; nf++){
                mma_bf16(acc[mf][nf][0], acc[mf][nf][1], acc[mf][nf][2], acc[mf][nf][3],
                         Ah[mf].x, Ah[mf].y, Ah[mf].z, Ah[mf].w, Bh[nf].x, Bh[nf].y);
                mma_bf16(acc[mf][nf][0], acc[mf][nf][1], acc[mf][nf][2], acc[mf][nf][3],
                         Ah[mf].x, Ah[mf].y, Ah[mf].z, Ah[mf].w, Bl[nf].x, Bl[nf].y);
                mma_bf16(acc[mf][nf][0], acc[mf][nf][1], acc[mf][nf][2], acc[mf][nf][3],
                         Al[mf].x, Al[mf].y, Al[mf].z, Al[mf].w, Bh[nf].x, Bh[nf].y);
            }
        if (g+1 < KG){
            #pragma unroll
            for (int mf=0; mf<4; mf++){ Ah[mf]=An[mf]; Al[mf]=Aln[mf]; }
            #pragma unroll
            for (int nf=0; nf<2; nf++){ Bh[nf]=Bn[nf]; Bl[nf]=Bln[nf]; }
        }
    }

    int r = lane >> 2, c2 = (lane & 3)*2;
    #pragma unroll
    for (int nf=0; nf<2; nf++){
        int n = (ni0+nf)*8 + c2;
        float2 bias = (n < Hh) ? *(const float2*)&bp[n] : *(const float2*)&ba[n-Hh];
        #pragma unroll
        for (int mf=0; mf<4; mf++){
            int m1 = (mi0+mf)*16 + r;
            int m2 = m1 + 8;
            __half2 v1 = __floats2half2_rn(acc[mf][nf][0] + bias.x, acc[mf][nf][1] + bias.y);
            __half2 v2 = __floats2half2_rn(acc[mf][nf][2] + bias.x, acc[mf][nf][3] + bias.y);
            if (n < Hh){
                *(__half2*)&g_hp_h[m1*Hh + n] = v1;
                *(__half2*)&g_hp_h[m2*Hh + n] = v2;
            } else {
                *(__half2*)&g_ha_h[m1*(Cc*Hh) + (n-Hh)] = v1;
                *(__half2*)&g_ha_h[m2*(Cc*Hh) + (n-Hh)] = v2;
            }
        }
    }
}

// ---------------------------------------------------------------------------
// biaffine partial: all-f16x2, 8-way h-split, tile 32p x 8a, 128 threads
// (thread = rows p and p+16 at column a). Direct half2 loads. Padded s_ha.
// grid = 1024: seg = bx&7; rest = bx>>3 -> b(2) x ptile(4) x atile(16)
// ---------------------------------------------------------------------------
__global__ __launch_bounds__(128,8) void k_biaffine(const float* __restrict__ Wout){
    __shared__ __half2 s_hp[32][JP2+1];
    __shared__ __half2 s_ha[Cc][JP2][9];   // pad 8->9: kills 8-way STS conflict
    __shared__ __half2 s_w[Cc][JP2];
    int bx = blockIdx.x;
    int seg  = bx & 7;
    int rest = bx >> 3;               // 0..127
    int b   = rest >> 6;
    int rem = rest & 63;
    int p0 = (rem >> 4) * 32;
    int a0 = (rem & 15) * 8;
    int tid = threadIdx.x;
    int p = tid >> 3, a = tid & 7;    // p 0..15, a 0..7
    int jbase = seg * JP2;

    const __half2* HP = reinterpret_cast<const __half2*>(g_hp_h);
    const __half2* HA = reinterpret_cast<const __half2*>(g_ha_h);

    #pragma unroll
    for (int i = 0; i < 12; i++){                 // 32*48 = 1536 half2
        int idx = tid + i*128;
        int r = idx / JP2, jp = idx % JP2;
        s_hp[r][jp] = HP[(b*Ss + p0 + r)*HH2 + jbase + jp];
    }
    #pragma unroll
    for (int i = 0; i < 15; i++){                 // 8*5*48 = 1920 half2
        int idx = tid + i*128;
        int al = idx / (Cc*JP2);
        int rr = idx % (Cc*JP2);
        int c = rr / JP2, jp = rr % JP2;
        s_ha[c][jp][al] = HA[((b*Ss + a0 + al)*Cc + c)*HH2 + jbase + jp];
    }
    for (int idx = tid; idx < Cc*JP2; idx += 128){
        int c = idx / JP2, jp = idx % JP2;
        float2 v = *(const float2*)&Wout[c*Hh + seg*HSEG + 2*jp];
        s_w[c][jp] = __floats2half2_rn(v.x, v.y);
    }
    __syncthreads();

    float fA[Cc] = {}, fB[Cc] = {};
    #pragma unroll 1
    for (int blk = 0; blk < 4; blk++){            // 4 blocks of 12 jp
        __half2 accA[Cc], accB[Cc];
        #pragma unroll
        for (int c=0;c<Cc;c++){
            accA[c] = __floats2half2_rn(0.f, 0.f);
            accB[c] = __floats2half2_rn(0.f, 0.f);
        }
        #pragma unroll
        for (int j=0;j<12;j++){
            int jp = blk*12 + j;
            __half2 hpA = s_hp[p][jp];
            __half2 hpB = s_hp[p+16][jp];
            #pragma unroll
            for (int c=0;c<Cc;c++){
                __half2 ha = s_ha[c][jp][a];
                __half2 w  = s_w[c][jp];
                __half2 xA = __hadd2(hpA, ha);
                __half2 xB = __hadd2(hpB, ha);
                unsigned tA, tB;
                asm("tanh.approx.f16x2 %0, %1;" : "=r"(tA) : "r"(*(unsigned*)&xA));
                asm("tanh.approx.f16x2 %0, %1;" : "=r"(tB) : "r"(*(unsigned*)&xB));
                accA[c] = __hfma2(*(__half2*)&tA, w, accA[c]);
                accB[c] = __hfma2(*(__half2*)&tB, w, accB[c]);
            }
        }
        #pragma unroll
        for (int c=0;c<Cc;c++){
            float2 vA = __half22float2(accA[c]);
            float2 vB = __half22float2(accB[c]);
            fA[c] += vA.x + vA.y;
            fB[c] += vB.x + vB.y;
        }
    }
    int pgA = p0 + p, pgB = p0 + p + 16, ag = a0 + a;
    #pragma unroll
    for (int c=0;c<Cc;c++){
        g_part[seg*OUTN + ((b*Ss+pgA)*Cc + c)*Ss + ag] = fA[c];
        g_part[seg*OUTN + ((b*Ss+pgB)*Cc + c)*Ss + ag] = fB[c];
    }
}

// ---------------------------------------------------------------------------
// combine: sum 8 partials + on-the-fly mask + fused log-softmax CE +
// last-block loss finalize.
// ---------------------------------------------------------------------------
#define NBLK (OUTN/256)   // 640

__global__ __launch_bounds__(256) void k_combine(const float* __restrict__ targ,
        const int* __restrict__ att, const void* __restrict__ ng,
        float* __restrict__ dst, float* __restrict__ out,
        int writeOut, int writeLoss){
    const unsigned FULL = 0xffffffffu;
    int tid = threadIdx.x;
    int i = blockIdx.x*256 + tid;
    float v = 0.f;
    #pragma unroll
    for (int k=0;k<SEG;k++) v += g_part[k*OUTN + i];

    int a = i & 127;
    int row = i >> 7;                 // (b*Ss+p)*Cc + c
    int bp = row / Cc;
    int b = bp >> 7;
    int mode = g_ngMode;
    bool attv = att[b*Ss + a] > 0;
    bool msk = false;
    #pragma unroll
    for (int c = 0; c < Cc; c++)
        msk = msk || ng_bit(ng, (bp*Cc + c)*Ss + a, mode);
    v += (msk && attv) ? 0.0f : NEGV;
    if (writeOut) dst[i] = v;

    int w = tid >> 5, lane = tid & 31, rg = tid >> 7;
    __shared__ float sA[8], sB[8];

    float m = v;
    #pragma unroll
    for (int o=16;o>0;o>>=1) m = fmaxf(m, __shfl_xor_sync(FULL,m,o));
    if (lane==0) sA[w] = m;
    __syncthreads();
    m = fmaxf(fmaxf(sA[rg*4+0],sA[rg*4+1]), fmaxf(sA[rg*4+2],sA[rg*4+3]));

    float e = __expf(v - m);
    float s = e;
    #pragma unroll
    for (int o=16;o>0;o>>=1) s += __shfl_xor_sync(FULL,s,o);
    if (lane==0) sB[w] = s;
    __syncthreads();
    s = sB[rg*4+0]+sB[rg*4+1]+sB[rg*4+2]+sB[rg*4+3];
    float logZ = __logf(s) + m;

    float tg = targ[i];
    float num = tg * (logZ - v);
    float den = tg;
    #pragma unroll
    for (int o=16;o>0;o>>=1){
        num += __shfl_xor_sync(FULL,num,o);
        den += __shfl_xor_sync(FULL,den,o);
    }
    __syncthreads();
    if (lane==0){ sA[w] = num; sB[w] = den; }
    __syncthreads();
    if ((tid & 127) == 0){
        int r = blockIdx.x*2 + rg;
        g_rnum[r] = sA[rg*4+0]+sA[rg*4+1]+sA[rg*4+2]+sA[rg*4+3];
        g_rden[r] = sB[rg*4+0]+sB[rg*4+1]+sB[rg*4+2]+sB[rg*4+3];
    }

    __threadfence();
    __shared__ unsigned s_rank;
    if (tid == 0) s_rank = atomicAdd(&g_ctr, 1u);
    __syncthreads();
    if (s_rank == NBLK-1){
        float n=0.f, d=0.f;
        for (int r = tid; r < NROWS; r += 256){ n += g_rnum[r]; d += g_rden[r]; }
        __shared__ float sn[256], sd[256];
        sn[tid]=n; sd[tid]=d; __syncthreads();
        for (int o=128;o>0;o>>=1){
            if (tid<o){ sn[tid]+=sn[tid+o]; sd[tid]+=sd[tid+o]; }
            __syncthreads();
        }
        if (tid==0){
            if (writeLoss) out[0] = sn[0]/sd[0];
            g_ctr = 0;
        }
    }
}

// ---------------------------------------------------------------------------
extern "C" void kernel_launch(void* const* d_in, const int* in_sizes, int n_in,
                              void* d_out, int out_size){
    const float*         seq  = (const float*)d_in[0];
    const int*           att  = (const int*)d_in[1];
    const unsigned char* ng   = (const unsigned char*)d_in[2];
    const float*         targ = (const float*)d_in[3];
    const float*         Wp   = (const float*)d_in[4];
    const float*         bp   = (const float*)d_in[5];
    const float*         Wa   = (const float*)d_in[6];
    const float*         ba   = (const float*)d_in[7];
    const float*         Wout = (const float*)d_in[8];
    float* out = (float*)d_out;

    k_prep<<<PREP_BLOCKS, 256>>>(seq, Wp, Wa, ng);
    k_gemm<<<dim3(NTOT/64, Mm/128), 256>>>(bp, ba);
    k_biaffine<<<1024, 128>>>(Wout);

    int wantLoss = (out_size != OUTN) ? 1 : 0;
    int wantOut  = (out_size >= OUTN) ? 1 : 0;
    float* dst = out + ((out_size > OUTN) ? 1 : 0);
    k_combine<<<NBLK, 256>>>(targ, att, (const void*)ng, dst, out, wantOut, wantLoss);
}

// round 12
// speedup vs baseline: 1.0974x; 1.0061x over previous
#include <cuda_runtime.h>
#include <cuda_bf16.h>
#include <cuda_fp16.h>
#include <math.h>

#define Bb 2
#define Ss 128
#define Hh 768
#define Cc 5
#define NEGV (-1024.0f)
#define Mm (Bb*Ss)          // 256
#define NTOT (Hh + Cc*Hh)   // 4608
#define NROWS (Bb*Ss*Cc)    // 1280
#define OUTN (Bb*Ss*Cc*Ss)  // 163840

#define KG  (Hh/16)         // 48
#define MI  (Mm/16)         // 16
#define NI8 (NTOT/8)        // 576

#define SEG 8
#define HSEG (Hh/SEG)       // 96
#define JP2 (HSEG/2)        // 48 half2 per segment
#define HH2 (Hh/2)          // 384

__device__ __half g_hp_h[Mm*Hh];
__device__ __half g_ha_h[Mm*Cc*Hh];
__device__ float g_part[SEG*OUTN];
__device__ float g_rnum[NROWS];
__device__ float g_rden[NROWS];
__device__ int   g_ngMode;
__device__ unsigned g_ctr;
__device__ unsigned g_Afh[KG*MI*32*4];
__device__ unsigned g_Afl[KG*MI*32*4];
__device__ unsigned g_Bfh[KG*NI8*32*2];
__device__ unsigned g_Bfl[KG*NI8*32*2];

__device__ __forceinline__ unsigned pack2(__nv_bfloat16 lo, __nv_bfloat16 hi){
    __nv_bfloat162 v; v.x = lo; v.y = hi;
    return *reinterpret_cast<unsigned*>(&v);
}
__device__ __forceinline__ void split_bf(float x, __nv_bfloat16& h, __nv_bfloat16& l){
    h = __float2bfloat16(x);
    l = __float2bfloat16(x - __bfloat162float(h));
}

// ---------------------------------------------------------------------------
// prep: bf16 hi/lo fragments; LAST BLOCK does ng dtype detection.
// ---------------------------------------------------------------------------
#define AW (KG*MI*32*4)      // 98304
#define BW (KG*NI8*32*2)     // 1769472
#define FRAGTOT (AW+BW)
#define PREP_BLOCKS (FRAGTOT/256 + 1)

__global__ __launch_bounds__(256) void k_prep(const float* __restrict__ X,
        const float* __restrict__ Wp, const float* __restrict__ Wa,
        const unsigned char* __restrict__ ng){
    if (blockIdx.x == PREP_BLOCKS-1){
        __shared__ int s_b1, s_f3;
        if (threadIdx.x == 0){ s_b1 = 0; s_f3 = 0; }
        __syncthreads();
        int b1 = 0, f3 = 0;
        for (int i = threadIdx.x; i < 16384; i += 256){
            unsigned char v = ng[i];
            int o = i & 3;
            if (o == 1 && v) b1 = 1;
            if (o == 3 && v == 0x3F) f3 = 1;
        }
        if (b1) s_b1 = 1;
        if (f3) s_f3 = 1;
        __syncthreads();
        if (threadIdx.x == 0) g_ngMode = s_b1 ? 0 : (s_f3 ? 2 : 1);
        return;
    }
    int idx = blockIdx.x*256 + threadIdx.x;
    if (idx < AW){
        int w = idx;
        int reg = w & 3, lane = (w>>2)&31;
        int tile = w>>7;
        int mi = tile % MI, g = tile / MI;
        int m = mi*16 + (lane>>2) + (reg&1)*8;
        int k = g*16 + (lane&3)*2 + (reg>>1)*8;
        float2 v = *(const float2*)&X[m*Hh + k];
        __nv_bfloat16 hx,lx,hy,ly;
        split_bf(v.x, hx, lx); split_bf(v.y, hy, ly);
        g_Afh[w] = pack2(hx, hy);
        g_Afl[w] = pack2(lx, ly);
    } else {
        int w = idx - AW;
        int reg = w & 1, lane = (w>>1)&31;
        int tile = w>>6;
        int ni = tile % NI8, g = tile / NI8;
        int n = ni*8 + (lane>>2);
        int k = g*16 + (lane&3)*2 + reg*8;
        float2 v = (n < Hh) ? *(const float2*)&Wp[n*Hh + k]
                            : *(const float2*)&Wa[(n-Hh)*Hh + k];
        __nv_bfloat16 hx,lx,hy,ly;
        split_bf(v.x, hx, lx); split_bf(v.y, hy, ly);
        g_Bfh[w] = pack2(hx, hy);
        g_Bfl[w] = pack2(lx, ly);
    }
}

// ---------------------------------------------------------------------------
// GEMM: mma m16n8k16 bf16, acc += Ah*Bh + Ah*Bl + Al*Bh, double-buffered.
// CTA tile 64(M) x 64(N), 8 warps = 2(M) x 4(N), warp tile 32x16. grid (72,4).
// ---------------------------------------------------------------------------
__device__ __forceinline__ void mma_bf16(float& d0, float& d1, float& d2, float& d3,
        unsigned a0, unsigned a1, unsigned a2, unsigned a3,
        unsigned b0, unsigned b1){
    asm volatile("mma.sync.aligned.m16n8k16.row.col.f32.bf16.bf16.f32 "
        "{%0,%1,%2,%3}, {%4,%5,%6,%7}, {%8,%9}, {%0,%1,%2,%3};"
        : "+f"(d0), "+f"(d1), "+f"(d2), "+f"(d3)
        : "r"(a0), "r"(a1), "r"(a2), "r"(a3), "r"(b0), "r"(b1));
}

__global__ __launch_bounds__(256) void k_gemm(const float* __restrict__ bp,
                                              const float* __restrict__ ba){
    int tid = threadIdx.x;
    int wid = tid >> 5, lane = tid & 31;
    int wr = wid >> 2, wc = wid & 3;
    int mi0 = blockIdx.y*4 + wr*2;
    int ni0 = blockIdx.x*8 + wc*2;

    float acc[2][2][4];
    #pragma unroll
    for (int i=0;i<2;i++) for (int j=0;j<2;j++) for (int q=0;q<4;q++) acc[i][j][q]=0.f;

    const uint4* pAh = reinterpret_cast<const uint4*>(g_Afh);
    const uint4* pAl = reinterpret_cast<const uint4*>(g_Afl);
    const uint2* pBh = reinterpret_cast<const uint2*>(g_Bfh);
    const uint2* pBl = reinterpret_cast<const uint2*>(g_Bfl);

    uint4 Ah[2], Al[2]; uint2 Bh[2], Bl[2];
    #pragma unroll
    for (int mf=0; mf<2; mf++){
        int t = (0*MI + mi0+mf)*32 + lane;
        Ah[mf] = pAh[t]; Al[mf] = pAl[t];
    }
    #pragma unroll
    for (int nf=0; nf<2; nf++){
        int t = (0*NI8 + ni0+nf)*32 + lane;
        Bh[nf] = pBh[t]; Bl[nf] = pBl[t];
    }

    for (int g = 0; g < KG; g++){
        uint4 An[2], Aln[2]; uint2 Bn[2], Bln[2];
        if (g+1 < KG){
            #pragma unroll
            for (int mf=0; mf<2; mf++){
                int t = ((g+1)*MI + mi0+mf)*32 + lane;
                An[mf] = pAh[t]; Aln[mf] = pAl[t];
            }
            #pragma unroll
            for (int nf=0; nf<2; nf++){
                int t = ((g+1)*NI8 + ni0+nf)*32 + lane;
                Bn[nf] = pBh[t]; Bln[nf] = pBl[t];
            }
        }
        #pragma unroll
        for (int mf=0; mf<2; mf++)
            #pragma unroll
            for (int nf=0; nf<2; nf++){
                mma_bf16(acc[mf][nf][0], acc[mf][nf][1], acc[mf][nf][2], acc[mf][nf][3],
                         Ah[mf].x, Ah[mf].y, Ah[mf].z, Ah[mf].w, Bh[nf].x, Bh[nf].y);
                mma_bf16(acc[mf][nf][0], acc[mf][nf][1], acc[mf][nf][2], acc[mf][nf][3],
                         Ah[mf].x, Ah[mf].y, Ah[mf].z, Ah[mf].w, Bl[nf].x, Bl[nf].y);
                mma_bf16(acc[mf][nf][0], acc[mf][nf][1], acc[mf][nf][2], acc[mf][nf][3],
                         Al[mf].x, Al[mf].y, Al[mf].z, Al[mf].w, Bh[nf].x, Bh[nf].y);
            }
        if (g+1 < KG){
            #pragma unroll
            for (int mf=0; mf<2; mf++){ Ah[mf]=An[mf]; Al[mf]=Aln[mf]; }
            #pragma unroll
            for (int nf=0; nf<2; nf++){ Bh[nf]=Bn[nf]; Bl[nf]=Bln[nf]; }
        }
    }

    int r = lane >> 2, c2 = (lane & 3)*2;
    #pragma unroll
    for (int nf=0; nf<2; nf++){
        int n = (ni0+nf)*8 + c2;
        float2 bias = (n < Hh) ? *(const float2*)&bp[n] : *(const float2*)&ba[n-Hh];
        #pragma unroll
        for (int mf=0; mf<2; mf++){
            int m1 = (mi0+mf)*16 + r;
            int m2 = m1 + 8;
            __half2 v1 = __floats2half2_rn(acc[mf][nf][0] + bias.x, acc[mf][nf][1] + bias.y);
            __half2 v2 = __floats2half2_rn(acc[mf][nf][2] + bias.x, acc[mf][nf][3] + bias.y);
            if (n < Hh){
                *(__half2*)&g_hp_h[m1*Hh + n] = v1;
                *(__half2*)&g_hp_h[m2*Hh + n] = v2;
            } else {
                *(__half2*)&g_ha_h[m1*(Cc*Hh) + (n-Hh)] = v1;
                *(__half2*)&g_ha_h[m2*(Cc*Hh) + (n-Hh)] = v2;
            }
        }
    }
}

// ---------------------------------------------------------------------------
// biaffine partial: all-f16x2, 8-way h-split, tile 32p x 8a, 128 threads,
// padded s_ha. grid 1024.
// ---------------------------------------------------------------------------
__global__ __launch_bounds__(128,8) void k_biaffine(const float* __restrict__ Wout){
    __shared__ __half2 s_hp[32][JP2+1];
    __shared__ __half2 s_ha[Cc][JP2][9];
    __shared__ __half2 s_w[Cc][JP2];
    int bx = blockIdx.x;
    int seg  = bx & 7;
    int rest = bx >> 3;
    int b   = rest >> 6;
    int rem = rest & 63;
    int p0 = (rem >> 4) * 32;
    int a0 = (rem & 15) * 8;
    int tid = threadIdx.x;
    int p = tid >> 3, a = tid & 7;
    int jbase = seg * JP2;

    const __half2* HP = reinterpret_cast<const __half2*>(g_hp_h);
    const __half2* HA = reinterpret_cast<const __half2*>(g_ha_h);

    #pragma unroll
    for (int i = 0; i < 12; i++){
        int idx = tid + i*128;
        int r = idx / JP2, jp = idx % JP2;
        s_hp[r][jp] = HP[(b*Ss + p0 + r)*HH2 + jbase + jp];
    }
    #pragma unroll
    for (int i = 0; i < 15; i++){
        int idx = tid + i*128;
        int al = idx / (Cc*JP2);
        int rr = idx % (Cc*JP2);
        int c = rr / JP2, jp = rr % JP2;
        s_ha[c][jp][al] = HA[((b*Ss + a0 + al)*Cc + c)*HH2 + jbase + jp];
    }
    for (int idx = tid; idx < Cc*JP2; idx += 128){
        int c = idx / JP2, jp = idx % JP2;
        float2 v = *(const float2*)&Wout[c*Hh + seg*HSEG + 2*jp];
        s_w[c][jp] = __floats2half2_rn(v.x, v.y);
    }
    __syncthreads();

    float fA[Cc] = {}, fB[Cc] = {};
    #pragma unroll 1
    for (int blk = 0; blk < 4; blk++){
        __half2 accA[Cc], accB[Cc];
        #pragma unroll
        for (int c=0;c<Cc;c++){
            accA[c] = __floats2half2_rn(0.f, 0.f);
            accB[c] = __floats2half2_rn(0.f, 0.f);
        }
        #pragma unroll
        for (int j=0;j<12;j++){
            int jp = blk*12 + j;
            __half2 hpA = s_hp[p][jp];
            __half2 hpB = s_hp[p+16][jp];
            #pragma unroll
            for (int c=0;c<Cc;c++){
                __half2 ha = s_ha[c][jp][a];
                __half2 w  = s_w[c][jp];
                __half2 xA = __hadd2(hpA, ha);
                __half2 xB = __hadd2(hpB, ha);
                unsigned tA, tB;
                asm("tanh.approx.f16x2 %0, %1;" : "=r"(tA) : "r"(*(unsigned*)&xA));
                asm("tanh.approx.f16x2 %0, %1;" : "=r"(tB) : "r"(*(unsigned*)&xB));
                accA[c] = __hfma2(*(__half2*)&tA, w, accA[c]);
                accB[c] = __hfma2(*(__half2*)&tB, w, accB[c]);
            }
        }
        #pragma unroll
        for (int c=0;c<Cc;c++){
            float2 vA = __half22float2(accA[c]);
            float2 vB = __half22float2(accB[c]);
            fA[c] += vA.x + vA.y;
            fB[c] += vB.x + vB.y;
        }
    }
    int pgA = p0 + p, pgB = p0 + p + 16, ag = a0 + a;
    #pragma unroll
    for (int c=0;c<Cc;c++){
        g_part[seg*OUTN + ((b*Ss+pgA)*Cc + c)*Ss + ag] = fA[c];
        g_part[seg*OUTN + ((b*Ss+pgB)*Cc + c)*Ss + ag] = fB[c];
    }
}

// ---------------------------------------------------------------------------
// combine: warp-per-row, vectorized loads; dst store has an alignment-safe
// scalar path (dst may be out+1 when loss is packed first).
// ---------------------------------------------------------------------------
#define CBLK (NROWS/8)   // 160

__global__ __launch_bounds__(256) void k_combine(const float* __restrict__ targ,
        const int* __restrict__ att, const void* __restrict__ ng,
        float* __restrict__ dst, float* __restrict__ out,
        int writeOut, int dstAligned, int writeLoss){
    const unsigned FULL = 0xffffffffu;
    int tid = threadIdx.x;
    int w = tid >> 5, lane = tid & 31;
    int row = blockIdx.x*8 + w;           // (b*Ss+p)*Cc + c
    int bp = row / Cc;
    int b = bp >> 7;
    int base = row*Ss + lane*4;

    float4 v = make_float4(0.f,0.f,0.f,0.f);
    #pragma unroll
    for (int k=0;k<SEG;k++){
        float4 t = *(const float4*)&g_part[k*OUTN + base];
        v.x += t.x; v.y += t.y; v.z += t.z; v.w += t.w;
    }

    int mode = g_ngMode;
    bool m0=false, m1=false, m2=false, m3=false;
    if (mode == 1){
        #pragma unroll
        for (int c=0;c<Cc;c++){
            int4 q = *(const int4*)&((const int*)ng)[(bp*Cc + c)*Ss + lane*4];
            m0 |= q.x!=0; m1 |= q.y!=0; m2 |= q.z!=0; m3 |= q.w!=0;
        }
    } else if (mode == 2){
        #pragma unroll
        for (int c=0;c<Cc;c++){
            float4 q = *(const float4*)&((const float*)ng)[(bp*Cc + c)*Ss + lane*4];
            m0 |= q.x!=0.f; m1 |= q.y!=0.f; m2 |= q.z!=0.f; m3 |= q.w!=0.f;
        }
    } else {
        #pragma unroll
        for (int c=0;c<Cc;c++){
            uchar4 q = *(const uchar4*)&((const unsigned char*)ng)[(bp*Cc + c)*Ss + lane*4];
            m0 |= q.x!=0; m1 |= q.y!=0; m2 |= q.z!=0; m3 |= q.w!=0;
        }
    }
    int4 av = *(const int4*)&att[b*Ss + lane*4];
    v.x += (m0 && av.x>0) ? 0.f : NEGV;
    v.y += (m1 && av.y>0) ? 0.f : NEGV;
    v.z += (m2 && av.z>0) ? 0.f : NEGV;
    v.w += (m3 && av.w>0) ? 0.f : NEGV;
    if (writeOut){
        if (dstAligned){
            *(float4*)&dst[base] = v;
        } else {
            dst[base+0] = v.x; dst[base+1] = v.y;
            dst[base+2] = v.z; dst[base+3] = v.w;
        }
    }

    float m = fmaxf(fmaxf(v.x, v.y), fmaxf(v.z, v.w));
    #pragma unroll
    for (int o=16;o>0;o>>=1) m = fmaxf(m, __shfl_xor_sync(FULL,m,o));
    float s = __expf(v.x-m) + __expf(v.y-m) + __expf(v.z-m) + __expf(v.w-m);
    #pragma unroll
    for (int o=16;o>0;o>>=1) s += __shfl_xor_sync(FULL,s,o);
    float logZ = __logf(s) + m;

    float4 tg = *(const float4*)&targ[base];
    float num = tg.x*(logZ-v.x) + tg.y*(logZ-v.y) + tg.z*(logZ-v.z) + tg.w*(logZ-v.w);
    float den = tg.x + tg.y + tg.z + tg.w;
    #pragma unroll
    for (int o=16;o>0;o>>=1){
        num += __shfl_xor_sync(FULL,num,o);
        den += __shfl_xor_sync(FULL,den,o);
    }
    if (lane == 0){ g_rnum[row] = num; g_rden[row] = den; }

    __threadfence();
    __syncthreads();
    __shared__ unsigned s_rank;
    if (tid == 0) s_rank = atomicAdd(&g_ctr, 1u);
    __syncthreads();
    if (s_rank == CBLK-1){
        float n=0.f, d=0.f;
        for (int r = tid; r < NROWS; r += 256){ n += g_rnum[r]; d += g_rden[r]; }
        __shared__ float sn[256], sd[256];
        sn[tid]=n; sd[tid]=d; __syncthreads();
        for (int o=128;o>0;o>>=1){
            if (tid<o){ sn[tid]+=sn[tid+o]; sd[tid]+=sd[tid+o]; }
            __syncthreads();
        }
        if (tid==0){
            if (writeLoss) out[0] = sn[0]/sd[0];
            g_ctr = 0;
        }
    }
}

// ---------------------------------------------------------------------------
extern "C" void kernel_launch(void* const* d_in, const int* in_sizes, int n_in,
                              void* d_out, int out_size){
    const float*         seq  = (const float*)d_in[0];
    const int*           att  = (const int*)d_in[1];
    const unsigned char* ng   = (const unsigned char*)d_in[2];
    const float*         targ = (const float*)d_in[3];
    const float*         Wp   = (const float*)d_in[4];
    const float*         bp   = (const float*)d_in[5];
    const float*         Wa   = (const float*)d_in[6];
    const float*         ba   = (const float*)d_in[7];
    const float*         Wout = (const float*)d_in[8];
    float* out = (float*)d_out;

    k_prep<<<PREP_BLOCKS, 256>>>(seq, Wp, Wa, ng);
    k_gemm<<<dim3(NTOT/64, Mm/64), 256>>>(bp, ba);
    k_biaffine<<<1024, 128>>>(Wout);

    int wantLoss   = (out_size != OUTN) ? 1 : 0;
    int wantOut    = (out_size >= OUTN) ? 1 : 0;
    int dstOffset  = (out_size > OUTN) ? 1 : 0;
    float* dst = out + dstOffset;
    k_combine<<<CBLK, 256>>>(targ, att, (const void*)ng, dst, out,
                             wantOut, dstOffset ? 0 : 1, wantLoss);
}

// round 13
// speedup vs baseline: 1.1074x; 1.0091x over previous
#include <cuda_runtime.h>
#include <cuda_bf16.h>
#include <cuda_fp16.h>
#include <math.h>

#define Bb 2
#define Ss 128
#define Hh 768
#define Cc 5
#define NEGV (-1024.0f)
#define Mm (Bb*Ss)          // 256
#define NTOT (Hh + Cc*Hh)   // 4608
#define NROWS (Bb*Ss*Cc)    // 1280
#define OUTN (Bb*Ss*Cc*Ss)  // 163840

#define KG  (Hh/16)         // 48
#define MI  (Mm/16)         // 16
#define NI8 (NTOT/8)        // 576

#define SEG 8
#define HSEG (Hh/SEG)       // 96
#define JP2 (HSEG/2)        // 48 half2 per segment
#define HH2 (Hh/2)          // 384

__device__ __half g_hp_h[Mm*Hh];
__device__ __half g_ha_h[Mm*Cc*Hh];
__device__ float g_part[SEG*OUTN];
__device__ int   g_ngMode;
__device__ unsigned g_ctr;
__device__ unsigned long long g_lnum;   // fixed-point CE numerator (2^-32)
__device__ unsigned long long g_lden;   // fixed-point CE denominator
__device__ unsigned g_Afh[KG*MI*32*4];
__device__ unsigned g_Afl[KG*MI*32*4];
__device__ unsigned g_Bfh[KG*NI8*32*2];
__device__ unsigned g_Bfl[KG*NI8*32*2];

__device__ __forceinline__ unsigned pack2(__nv_bfloat16 lo, __nv_bfloat16 hi){
    __nv_bfloat162 v; v.x = lo; v.y = hi;
    return *reinterpret_cast<unsigned*>(&v);
}
__device__ __forceinline__ void split_bf(float x, __nv_bfloat16& h, __nv_bfloat16& l){
    h = __float2bfloat16(x);
    l = __float2bfloat16(x - __bfloat162float(h));
}

// ---------------------------------------------------------------------------
// prep: coalesced loads, scattered fragment stores. Thread = (row, k2).
//   A: m = idx/HH2, k = 2*(idx%HH2)
//      mi=m>>4, g=k>>4; reg = ((m&15)>>3) | (((k&15)>>3)<<1);
//      lane = ((m&7)<<2) | (((k&15)>>1)&3)   [inverse of proven mapping]
//   B: n = idx/HH2, k = 2*(idx%HH2)
//      ni=n>>3, g=k>>4; reg = (k&15)>>3; lane = ((n&7)<<2) | (((k&15)>>1)&3)
// LAST BLOCK does ng dtype detection.
// ---------------------------------------------------------------------------
#define AW2 (Mm*HH2)         // 98304 threads (A)
#define BW2 (NTOT*HH2)       // 1769472 threads (B)
#define FRAGTOT (AW2+BW2)
#define PREP_BLOCKS (FRAGTOT/256 + 1)

__global__ __launch_bounds__(256) void k_prep(const float* __restrict__ X,
        const float* __restrict__ Wp, const float* __restrict__ Wa,
        const unsigned char* __restrict__ ng){
    if (blockIdx.x == PREP_BLOCKS-1){
        __shared__ int s_b1, s_f3;
        if (threadIdx.x == 0){ s_b1 = 0; s_f3 = 0; }
        __syncthreads();
        int b1 = 0, f3 = 0;
        for (int i = threadIdx.x; i < 16384; i += 256){
            unsigned char v = ng[i];
            int o = i & 3;
            if (o == 1 && v) b1 = 1;
            if (o == 3 && v == 0x3F) f3 = 1;
        }
        if (b1) s_b1 = 1;
        if (f3) s_f3 = 1;
        __syncthreads();
        if (threadIdx.x == 0) g_ngMode = s_b1 ? 0 : (s_f3 ? 2 : 1);
        return;
    }
    int idx = blockIdx.x*256 + threadIdx.x;
    if (idx < AW2){
        int m = idx / HH2, k2 = idx % HH2;
        int k = 2*k2;
        float2 v = *(const float2*)&X[m*Hh + k];
        int mi = m >> 4, g = k >> 4;
        int ml = m & 15, kl = k & 15;
        int reg  = (ml >> 3) | ((kl >> 3) << 1);
        int lane = ((m & 7) << 2) | ((kl >> 1) & 3);
        int w = ((g*MI + mi)*32 + lane)*4 + reg;
        __nv_bfloat16 hx,lx,hy,ly;
        split_bf(v.x, hx, lx); split_bf(v.y, hy, ly);
        g_Afh[w] = pack2(hx, hy);
        g_Afl[w] = pack2(lx, ly);
    } else {
        int t = idx - AW2;
        int n = t / HH2, k2 = t % HH2;
        int k = 2*k2;
        float2 v = (n < Hh) ? *(const float2*)&Wp[n*Hh + k]
                            : *(const float2*)&Wa[(n-Hh)*Hh + k];
        int ni = n >> 3, g = k >> 4;
        int kl = k & 15;
        int reg  = kl >> 3;
        int lane = ((n & 7) << 2) | ((kl >> 1) & 3);
        int w = ((g*NI8 + ni)*32 + lane)*2 + reg;
        __nv_bfloat16 hx,lx,hy,ly;
        split_bf(v.x, hx, lx); split_bf(v.y, hy, ly);
        g_Bfh[w] = pack2(hx, hy);
        g_Bfl[w] = pack2(lx, ly);
    }
}

// ---------------------------------------------------------------------------
// GEMM: mma m16n8k16 bf16, acc += Ah*Bh + Ah*Bl + Al*Bh, double-buffered.
// CTA tile 64(M) x 64(N), 8 warps = 2(M) x 4(N), warp tile 32x16. grid (72,4).
// ---------------------------------------------------------------------------
__device__ __forceinline__ void mma_bf16(float& d0, float& d1, float& d2, float& d3,
        unsigned a0, unsigned a1, unsigned a2, unsigned a3,
        unsigned b0, unsigned b1){
    asm volatile("mma.sync.aligned.m16n8k16.row.col.f32.bf16.bf16.f32 "
        "{%0,%1,%2,%3}, {%4,%5,%6,%7}, {%8,%9}, {%0,%1,%2,%3};"
        : "+f"(d0), "+f"(d1), "+f"(d2), "+f"(d3)
        : "r"(a0), "r"(a1), "r"(a2), "r"(a3), "r"(b0), "r"(b1));
}

__global__ __launch_bounds__(256) void k_gemm(const float* __restrict__ bp,
                                              const float* __restrict__ ba){
    int tid = threadIdx.x;
    int wid = tid >> 5, lane = tid & 31;
    int wr = wid >> 2, wc = wid & 3;
    int mi0 = blockIdx.y*4 + wr*2;
    int ni0 = blockIdx.x*8 + wc*2;

    float acc[2][2][4];
    #pragma unroll
    for (int i=0;i<2;i++) for (int j=0;j<2;j++) for (int q=0;q<4;q++) acc[i][j][q]=0.f;

    const uint4* pAh = reinterpret_cast<const uint4*>(g_Afh);
    const uint4* pAl = reinterpret_cast<const uint4*>(g_Afl);
    const uint2* pBh = reinterpret_cast<const uint2*>(g_Bfh);
    const uint2* pBl = reinterpret_cast<const uint2*>(g_Bfl);

    uint4 Ah[2], Al[2]; uint2 Bh[2], Bl[2];
    #pragma unroll
    for (int mf=0; mf<2; mf++){
        int t = (0*MI + mi0+mf)*32 + lane;
        Ah[mf] = pAh[t]; Al[mf] = pAl[t];
    }
    #pragma unroll
    for (int nf=0; nf<2; nf++){
        int t = (0*NI8 + ni0+nf)*32 + lane;
        Bh[nf] = pBh[t]; Bl[nf] = pBl[t];
    }

    for (int g = 0; g < KG; g++){
        uint4 An[2], Aln[2]; uint2 Bn[2], Bln[2];
        if (g+1 < KG){
            #pragma unroll
            for (int mf=0; mf<2; mf++){
                int t = ((g+1)*MI + mi0+mf)*32 + lane;
                An[mf] = pAh[t]; Aln[mf] = pAl[t];
            }
            #pragma unroll
            for (int nf=0; nf<2; nf++){
                int t = ((g+1)*NI8 + ni0+nf)*32 + lane;
                Bn[nf] = pBh[t]; Bln[nf] = pBl[t];
            }
        }
        #pragma unroll
        for (int mf=0; mf<2; mf++)
            #pragma unroll
            for (int nf=0; nf<2; nf++){
                mma_bf16(acc[mf][nf][0], acc[mf][nf][1], acc[mf][nf][2], acc[mf][nf][3],
                         Ah[mf].x, Ah[mf].y, Ah[mf].z, Ah[mf].w, Bh[nf].x, Bh[nf].y);
                mma_bf16(acc[mf][nf][0], acc[mf][nf][1], acc[mf][nf][2], acc[mf][nf][3],
                         Ah[mf].x, Ah[mf].y, Ah[mf].z, Ah[mf].w, Bl[nf].x, Bl[nf].y);
                mma_bf16(acc[mf][nf][0], acc[mf][nf][1], acc[mf][nf][2], acc[mf][nf][3],
                         Al[mf].x, Al[mf].y, Al[mf].z, Al[mf].w, Bh[nf].x, Bh[nf].y);
            }
        if (g+1 < KG){
            #pragma unroll
            for (int mf=0; mf<2; mf++){ Ah[mf]=An[mf]; Al[mf]=Aln[mf]; }
            #pragma unroll
            for (int nf=0; nf<2; nf++){ Bh[nf]=Bn[nf]; Bl[nf]=Bln[nf]; }
        }
    }

    int r = lane >> 2, c2 = (lane & 3)*2;
    #pragma unroll
    for (int nf=0; nf<2; nf++){
        int n = (ni0+nf)*8 + c2;
        float2 bias = (n < Hh) ? *(const float2*)&bp[n] : *(const float2*)&ba[n-Hh];
        #pragma unroll
        for (int mf=0; mf<2; mf++){
            int m1 = (mi0+mf)*16 + r;
            int m2 = m1 + 8;
            __half2 v1 = __floats2half2_rn(acc[mf][nf][0] + bias.x, acc[mf][nf][1] + bias.y);
            __half2 v2 = __floats2half2_rn(acc[mf][nf][2] + bias.x, acc[mf][nf][3] + bias.y);
            if (n < Hh){
                *(__half2*)&g_hp_h[m1*Hh + n] = v1;
                *(__half2*)&g_hp_h[m2*Hh + n] = v2;
            } else {
                *(__half2*)&g_ha_h[m1*(Cc*Hh) + (n-Hh)] = v1;
                *(__half2*)&g_ha_h[m2*(Cc*Hh) + (n-Hh)] = v2;
            }
        }
    }
}

// ---------------------------------------------------------------------------
// biaffine partial (unchanged, proven): all-f16x2, 8-way h-split,
// tile 32p x 8a, 128 threads, padded s_ha. grid 1024.
// ---------------------------------------------------------------------------
__global__ __launch_bounds__(128,8) void k_biaffine(const float* __restrict__ Wout){
    __shared__ __half2 s_hp[32][JP2+1];
    __shared__ __half2 s_ha[Cc][JP2][9];
    __shared__ __half2 s_w[Cc][JP2];
    int bx = blockIdx.x;
    int seg  = bx & 7;
    int rest = bx >> 3;
    int b   = rest >> 6;
    int rem = rest & 63;
    int p0 = (rem >> 4) * 32;
    int a0 = (rem & 15) * 8;
    int tid = threadIdx.x;
    int p = tid >> 3, a = tid & 7;
    int jbase = seg * JP2;

    const __half2* HP = reinterpret_cast<const __half2*>(g_hp_h);
    const __half2* HA = reinterpret_cast<const __half2*>(g_ha_h);

    #pragma unroll
    for (int i = 0; i < 12; i++){
        int idx = tid + i*128;
        int r = idx / JP2, jp = idx % JP2;
        s_hp[r][jp] = HP[(b*Ss + p0 + r)*HH2 + jbase + jp];
    }
    #pragma unroll
    for (int i = 0; i < 15; i++){
        int idx = tid + i*128;
        int al = idx / (Cc*JP2);
        int rr = idx % (Cc*JP2);
        int c = rr / JP2, jp = rr % JP2;
        s_ha[c][jp][al] = HA[((b*Ss + a0 + al)*Cc + c)*HH2 + jbase + jp];
    }
    for (int idx = tid; idx < Cc*JP2; idx += 128){
        int c = idx / JP2, jp = idx % JP2;
        float2 v = *(const float2*)&Wout[c*Hh + seg*HSEG + 2*jp];
        s_w[c][jp] = __floats2half2_rn(v.x, v.y);
    }
    __syncthreads();

    float fA[Cc] = {}, fB[Cc] = {};
    #pragma unroll 1
    for (int blk = 0; blk < 4; blk++){
        __half2 accA[Cc], accB[Cc];
        #pragma unroll
        for (int c=0;c<Cc;c++){
            accA[c] = __floats2half2_rn(0.f, 0.f);
            accB[c] = __floats2half2_rn(0.f, 0.f);
        }
        #pragma unroll
        for (int j=0;j<12;j++){
            int jp = blk*12 + j;
            __half2 hpA = s_hp[p][jp];
            __half2 hpB = s_hp[p+16][jp];
            #pragma unroll
            for (int c=0;c<Cc;c++){
                __half2 ha = s_ha[c][jp][a];
                __half2 w  = s_w[c][jp];
                __half2 xA = __hadd2(hpA, ha);
                __half2 xB = __hadd2(hpB, ha);
                unsigned tA, tB;
                asm("tanh.approx.f16x2 %0, %1;" : "=r"(tA) : "r"(*(unsigned*)&xA));
                asm("tanh.approx.f16x2 %0, %1;" : "=r"(tB) : "r"(*(unsigned*)&xB));
                accA[c] = __hfma2(*(__half2*)&tA, w, accA[c]);
                accB[c] = __hfma2(*(__half2*)&tB, w, accB[c]);
            }
        }
        #pragma unroll
        for (int c=0;c<Cc;c++){
            float2 vA = __half22float2(accA[c]);
            float2 vB = __half22float2(accB[c]);
            fA[c] += vA.x + vA.y;
            fB[c] += vB.x + vB.y;
        }
    }
    int pgA = p0 + p, pgB = p0 + p + 16, ag = a0 + a;
    #pragma unroll
    for (int c=0;c<Cc;c++){
        g_part[seg*OUTN + ((b*Ss+pgA)*Cc + c)*Ss + ag] = fA[c];
        g_part[seg*OUTN + ((b*Ss+pgB)*Cc + c)*Ss + ag] = fB[c];
    }
}

// ---------------------------------------------------------------------------
// combine: warp-per-row, 128-thread blocks (grid 320), vectorized loads.
// CE partials accumulated via DETERMINISTIC int64 fixed-point atomics
// (2^-32 scale; integer addition is associative -> replay-stable).
// Last block divides and resets.
// ---------------------------------------------------------------------------
#define CBLK (NROWS/4)   // 320
#define FPSCALE 4294967296.0

__global__ __launch_bounds__(128) void k_combine(const float* __restrict__ targ,
        const int* __restrict__ att, const void* __restrict__ ng,
        float* __restrict__ dst, float* __restrict__ out,
        int writeOut, int dstAligned, int writeLoss){
    const unsigned FULL = 0xffffffffu;
    int tid = threadIdx.x;
    int w = tid >> 5, lane = tid & 31;
    int row = blockIdx.x*4 + w;           // (b*Ss+p)*Cc + c
    int bp = row / Cc;
    int b = bp >> 7;
    int base = row*Ss + lane*4;

    float4 v = make_float4(0.f,0.f,0.f,0.f);
    #pragma unroll
    for (int k=0;k<SEG;k++){
        float4 t = *(const float4*)&g_part[k*OUTN + base];
        v.x += t.x; v.y += t.y; v.z += t.z; v.w += t.w;
    }

    int mode = g_ngMode;
    bool m0=false, m1=false, m2=false, m3=false;
    if (mode == 1){
        #pragma unroll
        for (int c=0;c<Cc;c++){
            int4 q = *(const int4*)&((const int*)ng)[(bp*Cc + c)*Ss + lane*4];
            m0 |= q.x!=0; m1 |= q.y!=0; m2 |= q.z!=0; m3 |= q.w!=0;
        }
    } else if (mode == 2){
        #pragma unroll
        for (int c=0;c<Cc;c++){
            float4 q = *(const float4*)&((const float*)ng)[(bp*Cc + c)*Ss + lane*4];
            m0 |= q.x!=0.f; m1 |= q.y!=0.f; m2 |= q.z!=0.f; m3 |= q.w!=0.f;
        }
    } else {
        #pragma unroll
        for (int c=0;c<Cc;c++){
            uchar4 q = *(const uchar4*)&((const unsigned char*)ng)[(bp*Cc + c)*Ss + lane*4];
            m0 |= q.x!=0; m1 |= q.y!=0; m2 |= q.z!=0; m3 |= q.w!=0;
        }
    }
    int4 av = *(const int4*)&att[b*Ss + lane*4];
    v.x += (m0 && av.x>0) ? 0.f : NEGV;
    v.y += (m1 && av.y>0) ? 0.f : NEGV;
    v.z += (m2 && av.z>0) ? 0.f : NEGV;
    v.w += (m3 && av.w>0) ? 0.f : NEGV;
    if (writeOut){
        if (dstAligned){
            *(float4*)&dst[base] = v;
        } else {
            dst[base+0] = v.x; dst[base+1] = v.y;
            dst[base+2] = v.z; dst[base+3] = v.w;
        }
    }

    float m = fmaxf(fmaxf(v.x, v.y), fmaxf(v.z, v.w));
    #pragma unroll
    for (int o=16;o>0;o>>=1) m = fmaxf(m, __shfl_xor_sync(FULL,m,o));
    float s = __expf(v.x-m) + __expf(v.y-m) + __expf(v.z-m) + __expf(v.w-m);
    #pragma unroll
    for (int o=16;o>0;o>>=1) s += __shfl_xor_sync(FULL,s,o);
    float logZ = __logf(s) + m;

    float4 tg = *(const float4*)&targ[base];
    float num = tg.x*(logZ-v.x) + tg.y*(logZ-v.y) + tg.z*(logZ-v.z) + tg.w*(logZ-v.w);
    float den = tg.x + tg.y + tg.z + tg.w;
    #pragma unroll
    for (int o=16;o>0;o>>=1){
        num += __shfl_xor_sync(FULL,num,o);
        den += __shfl_xor_sync(FULL,den,o);
    }
    if (lane == 0 && writeLoss){
        atomicAdd(&g_lnum, (unsigned long long)__double2ll_rn((double)num * FPSCALE));
        atomicAdd(&g_lden, (unsigned long long)__double2ll_rn((double)den * FPSCALE));
    }

    // last-block finalize: divide + reset (cheap — no row re-reads)
    __threadfence();
    __syncthreads();
    __shared__ unsigned s_rank;
    if (tid == 0) s_rank = atomicAdd(&g_ctr, 1u);
    __syncthreads();
    if (s_rank == CBLK-1 && tid == 0){
        if (writeLoss){
            double n = (double)(long long)g_lnum;
            double d = (double)(long long)g_lden;
            out[0] = (float)(n / d);
            g_lnum = 0ull; g_lden = 0ull;
        }
        g_ctr = 0;
    }
}

// ---------------------------------------------------------------------------
extern "C" void kernel_launch(void* const* d_in, const int* in_sizes, int n_in,
                              void* d_out, int out_size){
    const float*         seq  = (const float*)d_in[0];
    const int*           att  = (const int*)d_in[1];
    const unsigned char* ng   = (const unsigned char*)d_in[2];
    const float*         targ = (const float*)d_in[3];
    const float*         Wp   = (const float*)d_in[4];
    const float*         bp   = (const float*)d_in[5];
    const float*         Wa   = (const float*)d_in[6];
    const float*         ba   = (const float*)d_in[7];
    const float*         Wout = (const float*)d_in[8];
    float* out = (float*)d_out;

    k_prep<<<PREP_BLOCKS, 256>>>(seq, Wp, Wa, ng);
    k_gemm<<<dim3(NTOT/64, Mm/64), 256>>>(bp, ba);
    k_biaffine<<<1024, 128>>>(Wout);

    int wantLoss   = (out_size != OUTN) ? 1 : 0;
    int wantOut    = (out_size >= OUTN) ? 1 : 0;
    int dstOffset  = (out_size > OUTN) ? 1 : 0;
    float* dst = out + dstOffset;
    k_combine<<<CBLK, 128>>>(targ, att, (const void*)ng, dst, out,
                             wantOut, dstOffset ? 0 : 1, wantLoss);
}